// round 10
// baseline (speedup 1.0000x reference)
#include <cuda_runtime.h>

// ---------------------------------------------------------------------------
//   x:  [2, 512, 512] complex (separate real/imag f32 planes)
//   P:  [128, 128] f32;  I: [2, 49, 128, 128] f32;  Ns: [49, 2] int32
//   out: float32 [2, 49, 512, 512] = REAL PART of complex grads
//        (25,690,112 elements; harness casts complex64 -> float32)
//
// Fourier-domain restructuring:
//   X = fft2(x) carried unshifted; step k touches only a 128x128 window:
//     X[u0,u1] -= MU*scale_bwd * patch  (0.16)
//   grads[k] = ifft2(ifftshift(Z_k)) * 16, Z_k sparse -> two deferred passes,
//   final pass emits only the real part.
// ---------------------------------------------------------------------------

#define NOBJ 512
#define MM   128
#define NCH  49
#define NB   2

__device__ float2 g_tw[256];                         // exp(+2*pi*i*k/512), k<256
__device__ float2 g_xFT[NB * NOBJ * NOBJ];           // 4 MB
__device__ float2 g_patch[NCH * NB * MM * MM];       // 12.8 MB  [kb][r][c]
__device__ float2 g_T[(size_t)NCH * NB * NOBJ * MM]; // 51.4 MB  [kb][t][c]
__device__ float2 g_W[NB * MM * MM];                 // step ping
__device__ float2 g_W2[NB * MM * MM];                // step pong

__device__ __forceinline__ int clampi(int i, int n) {
    return i < 0 ? 0 : (i >= n ? n - 1 : i);
}

// Warp-cooperative radix-2 FFT, unit stride, data in shared memory.
// tw is base-512: index for stage s is pos << (9-s). INV => +i twiddles.
// (Bit-identical equivalence with a naive DFT engine established in R7/8.)
template <int L, int LOGL, bool INV>
__device__ __forceinline__ void warp_fft(float2* a, const float2* tw) {
    const int lane = threadIdx.x & 31;
    constexpr int NPT = L / 32;
    float2 v[NPT];
#pragma unroll
    for (int q = 0; q < NPT; q++) {
        int idx = lane + (q << 5);
        int r = (int)(__brev((unsigned)idx) >> (32 - LOGL));
        v[q] = a[r];
    }
    __syncwarp();
#pragma unroll
    for (int q = 0; q < NPT; q++) a[lane + (q << 5)] = v[q];
    __syncwarp();
#pragma unroll
    for (int s = 1; s <= LOGL; s++) {
        const int half = 1 << (s - 1);
#pragma unroll
        for (int t = 0; t < (L >> 6); t++) {
            int j = lane + (t << 5);
            int pos = j & (half - 1);
            int i0 = ((j >> (s - 1)) << s) + pos;
            int i1 = i0 + half;
            float2 w = tw[pos << (9 - s)];
            float wy = INV ? w.y : -w.y;
            float2 x0 = a[i0], x1 = a[i1];
            float tr = w.x * x1.x - wy * x1.y;
            float ti = w.x * x1.y + wy * x1.x;
            a[i0] = make_float2(x0.x + tr, x0.y + ti);
            a[i1] = make_float2(x0.x - tr, x0.y - ti);
        }
        __syncwarp();
    }
}

__global__ void k_init_tw() {
    int k = threadIdx.x;  // 256 threads
    double ang = 6.283185307179586476925286766559 * (double)k / 512.0;
    g_tw[k] = make_float2((float)cos(ang), (float)sin(ang));
}

// fft2(x) pass 1: axis-1 transforms. 128 blocks x 256 threads (8 warps/cols).
__global__ void __launch_bounds__(256) k_init_cols(const float* __restrict__ xr,
                                                   const float* __restrict__ xi,
                                                   int nx) {
    __shared__ float2 sm[8 * 520 + 256];
    float2* tw = sm + 8 * 520;
    int tid = threadIdx.x, w = tid >> 5, lane = tid & 31;
    tw[tid] = g_tw[tid];
    __syncthreads();
    int b = blockIdx.x >> 6;
    int c0 = (blockIdx.x & 63) << 3;
    int col = c0 + w;
    float2* a = sm + w * 520;
#pragma unroll
    for (int q = 0; q < 16; q++) {
        int j = lane + (q << 5);
        int idx = clampi(b * 262144 + j * 512 + col, nx);
        a[j] = make_float2(xr[idx], xi[idx]);
    }
    __syncwarp();
    warp_fft<512, 9, false>(a, tw);
    __syncthreads();
    for (int e = tid; e < 4096; e += 256) {      // transposed coalesced store
        int t = e >> 3, ww = e & 7;
        g_T[((size_t)b * 512 + t) * 512 + c0 + ww] = sm[ww * 520 + t];
    }
}

// fft2(x) pass 2: axis-2 transforms -> g_xFT (unshifted). 128 blocks x 256.
__global__ void __launch_bounds__(256) k_init_rows() {
    __shared__ float2 sm[8 * 520 + 256];
    float2* tw = sm + 8 * 520;
    int tid = threadIdx.x, w = tid >> 5, lane = tid & 31;
    tw[tid] = g_tw[tid];
    __syncthreads();
    int b = blockIdx.x >> 6;
    int f = ((blockIdx.x & 63) << 3) + w;
    float2* a = sm + w * 520;
    const float2* src = g_T + ((size_t)b * 512 + f) * 512;
#pragma unroll
    for (int q = 0; q < 16; q++) { int u = lane + (q << 5); a[u] = src[u]; }
    __syncwarp();
    warp_fft<512, 9, false>(a, tw);
    float2* dst = g_xFT + (size_t)b * 262144 + (size_t)f * 512;
#pragma unroll
    for (int q = 0; q < 16; q++) { int u = lane + (q << 5); dst[u] = a[u]; }
}

// Step pass A: window*P (ifftshift folded) -> axis-2 IFFT -> g_W transposed.
__global__ void __launch_bounds__(256) k_step_a(int k, const float* __restrict__ P,
                                                const int* __restrict__ Ns,
                                                int np_, int nns) {
    __shared__ float2 sm[8 * 132 + 256];
    float2* tw = sm + 8 * 132;
    int tid = threadIdx.x, w = tid >> 5, lane = tid & 31;
    tw[tid] = g_tw[tid];
    __syncthreads();
    int b = blockIdx.x >> 4;
    int j0base = (blockIdx.x & 15) << 3;
    int j0 = j0base + w;
    int kxl = 192 + Ns[clampi(2 * k, nns)];
    int kyl = 192 + Ns[clampi(2 * k + 1, nns)];
    int r = (j0 + 64) & 127;
    int u0 = (kxl + r + 256) & 511;
    float2* a = sm + w * 132;
    const float2* xrow = g_xFT + (size_t)b * 262144 + (size_t)u0 * 512;
#pragma unroll
    for (int q = 0; q < 4; q++) {
        int j1 = lane + (q << 5);
        int c = (j1 + 64) & 127;
        int u1 = (kyl + c + 256) & 511;
        float2 xv = xrow[u1];
        float p = P[clampi(r * 128 + c, np_)];
        a[j1] = make_float2(xv.x * p, xv.y * p);
    }
    __syncwarp();
    warp_fft<128, 7, true>(a, tw);
    __syncthreads();
    for (int e = tid; e < 1024; e += 256) {
        int n1 = e >> 3, ww = e & 7;
        g_W[(size_t)b * 16384 + n1 * 128 + j0base + ww] = sm[ww * 132 + n1];
    }
}

// Step pass B: axis-1 IFFT -> nonlinearity -> axis-1 FFT -> g_W2 transposed.
__global__ void __launch_bounds__(256) k_step_b(int k, const float* __restrict__ I,
                                                int ni) {
    __shared__ float2 sm[8 * 132 + 256];
    float2* tw = sm + 8 * 132;
    int tid = threadIdx.x, w = tid >> 5, lane = tid & 31;
    tw[tid] = g_tw[tid];
    __syncthreads();
    int b = blockIdx.x >> 4;
    int n1base = (blockIdx.x & 15) << 3;
    int n1 = n1base + w;
    float2* a = sm + w * 132;
    const float2* src = g_W + (size_t)b * 16384 + (size_t)n1 * 128;
#pragma unroll
    for (int q = 0; q < 4; q++) { int u = lane + (q << 5); a[u] = src[u]; }
    __syncwarp();
    warp_fft<128, 7, true>(a, tw);
    const float sA = 1.0f / 262144.0f;   // (1/128^2) * scale_fwd(=1/16)
    int Ibase = (b * NCH + k) * 16384;
#pragma unroll
    for (int q = 0; q < 4; q++) {
        int n0 = lane + (q << 5);
        float2 v = a[n0];
        float vr = v.x * sA, vi = v.y * sA;
        float m = vr * vr + vi * vi - I[clampi(Ibase + n0 * 128 + n1, ni)];
        a[n0] = make_float2(m * vr, m * vi);
    }
    __syncwarp();
    warp_fft<128, 7, false>(a, tw);
    __syncthreads();
    for (int e = tid; e < 1024; e += 256) {
        int m0 = e >> 3, ww = e & 7;
        g_W2[(size_t)b * 16384 + m0 * 128 + n1base + ww] = sm[ww * 132 + m0];
    }
}

// Step pass C: axis-2 FFT -> patch = fftshift(F)*P; store patch; update X.
__global__ void __launch_bounds__(256) k_step_c(int k, const float* __restrict__ P,
                                                const int* __restrict__ Ns,
                                                int np_, int nns) {
    __shared__ float2 sm[8 * 132 + 256];
    float2* tw = sm + 8 * 132;
    int tid = threadIdx.x, w = tid >> 5, lane = tid & 31;
    tw[tid] = g_tw[tid];
    __syncthreads();
    int b = blockIdx.x >> 4;
    int m0 = ((blockIdx.x & 15) << 3) + w;
    float2* a = sm + w * 132;
    const float2* src = g_W2 + (size_t)b * 16384 + (size_t)m0 * 128;
#pragma unroll
    for (int q = 0; q < 4; q++) { int u = lane + (q << 5); a[u] = src[u]; }
    __syncwarp();
    warp_fft<128, 7, false>(a, tw);
    int kxl = 192 + Ns[clampi(2 * k, nns)];
    int kyl = 192 + Ns[clampi(2 * k + 1, nns)];
    int r = (m0 + 64) & 127;
    int u0 = (kxl + r + 256) & 511;
    int kb = k * NB + b;
    float2* patch_row = g_patch + (size_t)kb * 16384 + r * 128;
    float2* xrow = g_xFT + (size_t)b * 262144 + (size_t)u0 * 512;
#pragma unroll
    for (int q = 0; q < 4; q++) {
        int m1 = lane + (q << 5);
        int c = (m1 + 64) & 127;
        float p = P[clampi(r * 128 + c, np_)];
        float2 f = a[m1];
        float2 patch = make_float2(f.x * p, f.y * p);
        patch_row[c] = patch;
        int u1 = (kyl + c + 256) & 511;
        float2 xv = xrow[u1];
        xrow[u1] = make_float2(xv.x - 0.16f * patch.x, xv.y - 0.16f * patch.y);
    }
}

// Grad pass 1: sparse axis-1 IFFT (128 nonzero rows -> 512). 1568 blocks x 256.
__global__ void __launch_bounds__(256) k_grad1(const int* __restrict__ Ns, int nns) {
    __shared__ float2 sm[8 * 520 + 256];
    float2* tw = sm + 8 * 520;
    int tid = threadIdx.x, w = tid >> 5, lane = tid & 31;
    tw[tid] = g_tw[tid];
    __syncthreads();
    int kb = blockIdx.x >> 4;
    int k = kb >> 1;
    int c0 = (blockIdx.x & 15) << 3;
    int c = c0 + w;
    int kxl = 192 + Ns[clampi(2 * k, nns)];
    float2* a = sm + w * 520;
#pragma unroll
    for (int q = 0; q < 16; q++) a[lane + (q << 5)] = make_float2(0.f, 0.f);
    __syncwarp();
    for (int r = lane; r < 128; r += 32) {
        int u0 = (kxl + r + 256) & 511;
        a[u0] = g_patch[(size_t)kb * 16384 + r * 128 + c];
    }
    __syncwarp();
    warp_fft<512, 9, true>(a, tw);
    __syncthreads();
    for (int e = tid; e < 4096; e += 256) {
        int t = e >> 3, ww = e & 7;
        g_T[((size_t)kb * 512 + t) * 128 + c0 + ww] = sm[ww * 520 + t];
    }
}

// Grad pass 2: sparse axis-2 IFFT -> REAL PART only, scaled, to output.
// 6272 blocks x 256 threads; warp = one (kb, row t).
__global__ void __launch_bounds__(256) k_grad2(const int* __restrict__ Ns, int nns,
                                               float* __restrict__ outf,
                                               int n_out) {
    __shared__ float2 sm[8 * 520 + 256];
    float2* tw = sm + 8 * 520;
    int tid = threadIdx.x, w = tid >> 5, lane = tid & 31;
    tw[tid] = g_tw[tid];
    __syncthreads();
    int kb = blockIdx.x >> 6;
    int t = ((blockIdx.x & 63) << 3) + w;
    int k = kb >> 1, b = kb & 1;
    int kyl = 192 + Ns[clampi(2 * k + 1, nns)];
    float2* a = sm + w * 520;
#pragma unroll
    for (int q = 0; q < 16; q++) a[lane + (q << 5)] = make_float2(0.f, 0.f);
    __syncwarp();
    const float2* src = g_T + ((size_t)kb * 512 + t) * 128;
    for (int c = lane; c < 128; c += 32) {
        int u1 = (kyl + c + 256) & 511;
        a[u1] = src[c];
    }
    __syncwarp();
    warp_fft<512, 9, true>(a, tw);
    const float s = 1.0f / 16384.0f;        // (1/512^2) * scale_bwd(=16)
    long long base = (((long long)b * NCH + k) * 512 + t) * 512;
#pragma unroll
    for (int q = 0; q < 16; q++) {
        int u = lane + (q << 5);
        long long idx = base + u;           // float32 element index
        if (idx < (long long)n_out) {
            outf[idx] = a[u].x * s;         // REAL part only
        }
    }
}

// ---------------------------------------------------------------------------
extern "C" void kernel_launch(void* const* d_in, const int* in_sizes, int n_in,
                              void* d_out, int out_size) {
    // Bind by element count. The two 524288 buffers: FIRST = x_real,
    // SECOND = x_imag (dict/signature order).
    const float *xr = nullptr, *xi = nullptr, *P = nullptr, *I = nullptr;
    const int* Ns = nullptr;
    int nx = 0, np_ = 0, ni = 0, nns = 0;
    for (int i = 0; i < n_in; i++) {
        int sz = in_sizes[i];
        if (sz == 524288) {
            if (!xr) { xr = (const float*)d_in[i]; nx = sz; }
            else if (!xi) xi = (const float*)d_in[i];
        } else if (sz == 16384) { P = (const float*)d_in[i]; np_ = sz; }
        else if (sz == 1605632) { I = (const float*)d_in[i]; ni = sz; }
        else if (sz == 98)      { Ns = (const int*)d_in[i]; nns = sz; }
    }
    if (!xr || !xi || !P || !I || !Ns) return;
    float* outf = (float*)d_out;

    k_init_tw<<<1, 256>>>();
    k_init_cols<<<128, 256>>>(xr, xi, nx);
    k_init_rows<<<128, 256>>>();
    for (int k = 0; k < NCH; k++) {
        k_step_a<<<32, 256>>>(k, P, Ns, np_, nns);
        k_step_b<<<32, 256>>>(k, I, ni);
        k_step_c<<<32, 256>>>(k, P, Ns, np_, nns);
    }
    k_grad1<<<1568, 256>>>(Ns, nns);
    k_grad2<<<6272, 256>>>(Ns, nns, outf, out_size);
}

// round 11
// speedup vs baseline: 1.0975x; 1.0975x over previous
#include <cuda_runtime.h>

// ---------------------------------------------------------------------------
//   x:  [2, 512, 512] complex (separate real/imag f32 planes)
//   P:  [128, 128] f32;  I: [2, 49, 128, 128] f32;  Ns: [49, 2] int32
//   out: float32 [2, 49, 512, 512] = REAL PART of complex grads (25,690,112)
//
// Fourier-domain restructuring:
//   X = fft2(x) carried unshifted; step k touches only a 128x128 window:
//     X[u0,u1] -= MU*scale_bwd * patch  (0.16)
//   grads[k] = ifft2(ifftshift(Z_k)) * 16, Z_k sparse -> two deferred passes,
//   final pass emits only the real part.
//
// R10->R11: the 147-launch serial step chain (90% of runtime, 7.3us/launch of
// pure overhead) becomes ONE persistent kernel with software grid barriers.
// ---------------------------------------------------------------------------

#define NOBJ 512
#define MM   128
#define NCH  49
#define NB   2

__device__ float2 g_tw[256];                         // exp(+2*pi*i*k/512), k<256
__device__ float2 g_xFT[NB * NOBJ * NOBJ];           // 4 MB
__device__ float2 g_patch[NCH * NB * MM * MM];       // 12.8 MB  [kb][r][c]
__device__ float2 g_T[(size_t)NCH * NB * NOBJ * MM]; // 51.4 MB  [kb][t][c]
__device__ float2 g_W[NB * MM * MM];                 // step ping
__device__ float2 g_W2[NB * MM * MM];                // step pong
__device__ int    g_bar[NB][3 * NCH];                // barrier slots (zeroed/run)

__device__ __forceinline__ int clampi(int i, int n) {
    return i < 0 ? 0 : (i >= n ? n - 1 : i);
}

// Warp-cooperative radix-2 FFT, unit stride, data in shared memory.
// tw is base-512: index for stage s is pos << (9-s). INV => +i twiddles.
template <int L, int LOGL, bool INV>
__device__ __forceinline__ void warp_fft(float2* a, const float2* tw) {
    const int lane = threadIdx.x & 31;
    constexpr int NPT = L / 32;
    float2 v[NPT];
#pragma unroll
    for (int q = 0; q < NPT; q++) {
        int idx = lane + (q << 5);
        int r = (int)(__brev((unsigned)idx) >> (32 - LOGL));
        v[q] = a[r];
    }
    __syncwarp();
#pragma unroll
    for (int q = 0; q < NPT; q++) a[lane + (q << 5)] = v[q];
    __syncwarp();
#pragma unroll
    for (int s = 1; s <= LOGL; s++) {
        const int half = 1 << (s - 1);
#pragma unroll
        for (int t = 0; t < (L >> 6); t++) {
            int j = lane + (t << 5);
            int pos = j & (half - 1);
            int i0 = ((j >> (s - 1)) << s) + pos;
            int i1 = i0 + half;
            float2 w = tw[pos << (9 - s)];
            float wy = INV ? w.y : -w.y;
            float2 x0 = a[i0], x1 = a[i1];
            float tr = w.x * x1.x - wy * x1.y;
            float ti = w.x * x1.y + wy * x1.x;
            a[i0] = make_float2(x0.x + tr, x0.y + ti);
            a[i1] = make_float2(x0.x - tr, x0.y - ti);
        }
        __syncwarp();
    }
}

__global__ void k_init_tw() {
    int k = threadIdx.x;  // 256 threads
    double ang = 6.283185307179586476925286766559 * (double)k / 512.0;
    g_tw[k] = make_float2((float)cos(ang), (float)sin(ang));
}

__global__ void k_zero_bar() {
    int i = threadIdx.x;
    if (i < 3 * NCH) { g_bar[0][i] = 0; g_bar[1][i] = 0; }
}

// fft2(x) pass 1: axis-1 transforms. 128 blocks x 256 threads (8 warps/cols).
__global__ void __launch_bounds__(256) k_init_cols(const float* __restrict__ xr,
                                                   const float* __restrict__ xi,
                                                   int nx) {
    __shared__ float2 sm[8 * 520 + 256];
    float2* tw = sm + 8 * 520;
    int tid = threadIdx.x, w = tid >> 5, lane = tid & 31;
    tw[tid] = g_tw[tid];
    __syncthreads();
    int b = blockIdx.x >> 6;
    int c0 = (blockIdx.x & 63) << 3;
    int col = c0 + w;
    float2* a = sm + w * 520;
#pragma unroll
    for (int q = 0; q < 16; q++) {
        int j = lane + (q << 5);
        int idx = clampi(b * 262144 + j * 512 + col, nx);
        a[j] = make_float2(xr[idx], xi[idx]);
    }
    __syncwarp();
    warp_fft<512, 9, false>(a, tw);
    __syncthreads();
    for (int e = tid; e < 4096; e += 256) {      // transposed coalesced store
        int t = e >> 3, ww = e & 7;
        g_T[((size_t)b * 512 + t) * 512 + c0 + ww] = sm[ww * 520 + t];
    }
}

// fft2(x) pass 2: axis-2 transforms -> g_xFT (unshifted). 128 blocks x 256.
__global__ void __launch_bounds__(256) k_init_rows() {
    __shared__ float2 sm[8 * 520 + 256];
    float2* tw = sm + 8 * 520;
    int tid = threadIdx.x, w = tid >> 5, lane = tid & 31;
    tw[tid] = g_tw[tid];
    __syncthreads();
    int b = blockIdx.x >> 6;
    int f = ((blockIdx.x & 63) << 3) + w;
    float2* a = sm + w * 520;
    const float2* src = g_T + ((size_t)b * 512 + f) * 512;
#pragma unroll
    for (int q = 0; q < 16; q++) { int u = lane + (q << 5); a[u] = src[u]; }
    __syncwarp();
    warp_fft<512, 9, false>(a, tw);
    float2* dst = g_xFT + (size_t)b * 262144 + (size_t)f * 512;
#pragma unroll
    for (int q = 0; q < 16; q++) { int u = lane + (q << 5); dst[u] = a[u]; }
}

// ---------------------------------------------------------------------------
// Persistent chain kernel: 32 blocks (16 per b) x 256 threads, loops k=0..48
// with 3 software grid barriers per step (per-b, 16 arrivals each).
// Cross-block data (g_xFT, g_W, g_W2) is read with __ldcg (L1 may be stale
// within a single launch); global stores are L2-visible after __threadfence.
// ---------------------------------------------------------------------------
__device__ __forceinline__ void chain_barrier(int b, int slot) {
    __threadfence();                 // all my stores -> device scope
    __syncthreads();                 // every thread in block has fenced
    if (threadIdx.x == 0) {
        atomicAdd(&g_bar[b][slot], 1);
        volatile int* p = &g_bar[b][slot];
        while (*p < 16) { }
    }
    __syncthreads();
}

__global__ void __launch_bounds__(256) k_chain(const float* __restrict__ P,
                                               const float* __restrict__ I,
                                               const int* __restrict__ Ns) {
    __shared__ float2 sm[8 * 132];
    __shared__ float2 tw[256];
    int tid = threadIdx.x, w = tid >> 5, lane = tid & 31;
    tw[tid] = g_tw[tid];
    __syncthreads();
    int b = blockIdx.x >> 4;
    int blk = blockIdx.x & 15;
    float2* a = sm + w * 132;

    for (int k = 0; k < NCH; k++) {
        int kxl = 192 + Ns[2 * k];
        int kyl = 192 + Ns[2 * k + 1];

        // ---- phase 1: window*P (ifftshift folded) -> row IFFT -> g_W^T ----
        {
            int j0 = (blk << 3) + w;               // 0..127
            int r = (j0 + 64) & 127;
            int u0 = (kxl + r + 256) & 511;
            const float2* xrow = g_xFT + (size_t)b * 262144 + (size_t)u0 * 512;
            const float* prow = P + r * 128;
#pragma unroll
            for (int q = 0; q < 4; q++) {
                int j1 = lane + (q << 5);
                int c = (j1 + 64) & 127;
                int u1 = (kyl + c + 256) & 511;
                float2 xv = __ldcg(&xrow[u1]);
                float p = prow[c];
                a[j1] = make_float2(xv.x * p, xv.y * p);
            }
            __syncwarp();
            warp_fft<128, 7, true>(a, tw);
            __syncthreads();
            for (int e = tid; e < 1024; e += 256) {
                int n1 = e >> 3, ww = e & 7;
                g_W[(size_t)b * 16384 + n1 * 128 + (blk << 3) + ww] = sm[ww * 132 + n1];
            }
        }
        chain_barrier(b, 3 * k + 0);

        // ---- phase 2: col IFFT -> nonlinearity -> col FFT -> g_W2^T ----
        {
            int n1 = (blk << 3) + w;
            const float2* src = g_W + (size_t)b * 16384 + (size_t)n1 * 128;
#pragma unroll
            for (int q = 0; q < 4; q++) { int u = lane + (q << 5); a[u] = __ldcg(&src[u]); }
            __syncwarp();
            warp_fft<128, 7, true>(a, tw);
            const float sA = 1.0f / 262144.0f;     // (1/128^2) * scale_fwd(=1/16)
            const float* Ik = I + ((size_t)b * NCH + k) * 16384;
#pragma unroll
            for (int q = 0; q < 4; q++) {
                int n0 = lane + (q << 5);
                float2 v = a[n0];
                float vr = v.x * sA, vi = v.y * sA;
                float m = vr * vr + vi * vi - Ik[n0 * 128 + n1];
                a[n0] = make_float2(m * vr, m * vi);
            }
            __syncwarp();
            warp_fft<128, 7, false>(a, tw);
            __syncthreads();
            for (int e = tid; e < 1024; e += 256) {
                int m0 = e >> 3, ww = e & 7;
                g_W2[(size_t)b * 16384 + m0 * 128 + (blk << 3) + ww] = sm[ww * 132 + m0];
            }
        }
        chain_barrier(b, 3 * k + 1);

        // ---- phase 3: row FFT -> patch = fftshift(F)*P; update xFT ----
        {
            int m0 = (blk << 3) + w;
            const float2* src = g_W2 + (size_t)b * 16384 + (size_t)m0 * 128;
#pragma unroll
            for (int q = 0; q < 4; q++) { int u = lane + (q << 5); a[u] = __ldcg(&src[u]); }
            __syncwarp();
            warp_fft<128, 7, false>(a, tw);
            int r = (m0 + 64) & 127;
            int u0 = (kxl + r + 256) & 511;
            int kb = k * NB + b;
            float2* patch_row = g_patch + (size_t)kb * 16384 + r * 128;
            float2* xrow = g_xFT + (size_t)b * 262144 + (size_t)u0 * 512;
            const float* prow = P + r * 128;
#pragma unroll
            for (int q = 0; q < 4; q++) {
                int m1 = lane + (q << 5);
                int c = (m1 + 64) & 127;
                float p = prow[c];
                float2 f = a[m1];
                float2 patch = make_float2(f.x * p, f.y * p);
                patch_row[c] = patch;
                int u1 = (kyl + c + 256) & 511;
                float2 xv = __ldcg(&xrow[u1]);
                xrow[u1] = make_float2(xv.x - 0.16f * patch.x, xv.y - 0.16f * patch.y);
            }
        }
        chain_barrier(b, 3 * k + 2);
    }
}

// Grad pass 1: sparse axis-1 IFFT (128 nonzero rows -> 512). 1568 blocks x 256.
__global__ void __launch_bounds__(256) k_grad1(const int* __restrict__ Ns, int nns) {
    __shared__ float2 sm[8 * 520 + 256];
    float2* tw = sm + 8 * 520;
    int tid = threadIdx.x, w = tid >> 5, lane = tid & 31;
    tw[tid] = g_tw[tid];
    __syncthreads();
    int kb = blockIdx.x >> 4;
    int k = kb >> 1;
    int c0 = (blockIdx.x & 15) << 3;
    int c = c0 + w;
    int kxl = 192 + Ns[clampi(2 * k, nns)];
    float2* a = sm + w * 520;
#pragma unroll
    for (int q = 0; q < 16; q++) a[lane + (q << 5)] = make_float2(0.f, 0.f);
    __syncwarp();
    for (int r = lane; r < 128; r += 32) {
        int u0 = (kxl + r + 256) & 511;
        a[u0] = g_patch[(size_t)kb * 16384 + r * 128 + c];
    }
    __syncwarp();
    warp_fft<512, 9, true>(a, tw);
    __syncthreads();
    for (int e = tid; e < 4096; e += 256) {
        int t = e >> 3, ww = e & 7;
        g_T[((size_t)kb * 512 + t) * 128 + c0 + ww] = sm[ww * 520 + t];
    }
}

// Grad pass 2: sparse axis-2 IFFT -> REAL PART only, scaled, to output.
__global__ void __launch_bounds__(256) k_grad2(const int* __restrict__ Ns, int nns,
                                               float* __restrict__ outf,
                                               int n_out) {
    __shared__ float2 sm[8 * 520 + 256];
    float2* tw = sm + 8 * 520;
    int tid = threadIdx.x, w = tid >> 5, lane = tid & 31;
    tw[tid] = g_tw[tid];
    __syncthreads();
    int kb = blockIdx.x >> 6;
    int t = ((blockIdx.x & 63) << 3) + w;
    int k = kb >> 1, b = kb & 1;
    int kyl = 192 + Ns[clampi(2 * k + 1, nns)];
    float2* a = sm + w * 520;
#pragma unroll
    for (int q = 0; q < 16; q++) a[lane + (q << 5)] = make_float2(0.f, 0.f);
    __syncwarp();
    const float2* src = g_T + ((size_t)kb * 512 + t) * 128;
    for (int c = lane; c < 128; c += 32) {
        int u1 = (kyl + c + 256) & 511;
        a[u1] = src[c];
    }
    __syncwarp();
    warp_fft<512, 9, true>(a, tw);
    const float s = 1.0f / 16384.0f;        // (1/512^2) * scale_bwd(=16)
    long long base = (((long long)b * NCH + k) * 512 + t) * 512;
#pragma unroll
    for (int q = 0; q < 16; q++) {
        int u = lane + (q << 5);
        long long idx = base + u;           // float32 element index
        if (idx < (long long)n_out) {
            outf[idx] = a[u].x * s;         // REAL part only
        }
    }
}

// ---------------------------------------------------------------------------
extern "C" void kernel_launch(void* const* d_in, const int* in_sizes, int n_in,
                              void* d_out, int out_size) {
    // Bind by element count. The two 524288 buffers: FIRST = x_real,
    // SECOND = x_imag (dict/signature order — verified passing in R10).
    const float *xr = nullptr, *xi = nullptr, *P = nullptr, *I = nullptr;
    const int* Ns = nullptr;
    int nx = 0, np_ = 0, ni = 0, nns = 0;
    for (int i = 0; i < n_in; i++) {
        int sz = in_sizes[i];
        if (sz == 524288) {
            if (!xr) { xr = (const float*)d_in[i]; nx = sz; }
            else if (!xi) xi = (const float*)d_in[i];
        } else if (sz == 16384) { P = (const float*)d_in[i]; np_ = sz; }
        else if (sz == 1605632) { I = (const float*)d_in[i]; ni = sz; }
        else if (sz == 98)      { Ns = (const int*)d_in[i]; nns = sz; }
    }
    if (!xr || !xi || !P || !I || !Ns) return;
    (void)np_; (void)ni;
    float* outf = (float*)d_out;

    k_init_tw<<<1, 256>>>();
    k_zero_bar<<<1, 256>>>();
    k_init_cols<<<128, 256>>>(xr, xi, nx);
    k_init_rows<<<128, 256>>>();
    k_chain<<<32, 256>>>(P, I, Ns);
    k_grad1<<<1568, 256>>>(Ns, nns);
    k_grad2<<<6272, 256>>>(Ns, nns, outf, out_size);
}